// round 5
// baseline (speedup 1.0000x reference)
#include <cuda_runtime.h>
#include <cstdint>

// Problem constants
#define BATCH   8
#define SEQ     4096
#define MROWS   (BATCH*SEQ)     // 32768
#define DIM     768
#define VPOS    10240
#define POS_OFF ((size_t)VPOS * DIM)   // offset of pos_table[1]

// GEMM tiling
#define BM 128
#define BN 128
#define BK 32
#define STRIDE 36               // smem row stride in floats (padded)
#define ASZ (BM*STRIDE)         // 4608 floats
#define STAGE_F (2*ASZ)         // A + B per stage = 9216 floats
#define SMEM_BYTES (2*STAGE_F*4)  // 73728 bytes, double buffered

// Output layout (flattened concat of the reference tuple, as float32)
#define OUT_Y     ((size_t)MROWS * DIM)      // 25165824
#define OUT_PID   ((size_t)MROWS * 2)        // 65536
#define OUT_PAD   ((size_t)MROWS)            // 32768
#define OUT_TOTAL (OUT_Y + OUT_PID + OUT_PAD)

// Device scratch (allocation-free rule: __device__ globals)
__device__ float g_Wp[DIM * DIM];   // permuted, x2, tf32-rounded weights [d][j]
__device__ float g_bias[DIM];       // -sum_k W[d,k]

// Normalized index/validity scratch (input-dtype agnostic)
__device__ int g_pid0[MROWS];       // clamped index into pos_table[0] (= max(coord1,0))
__device__ int g_pid1[MROWS];       // clamped index into pos_table[1] (= max(coord0,0))
__device__ int g_rawc0[MROWS];      // raw coord[...,0] for aux output
__device__ int g_rawc1[MROWS];      // raw coord[...,1] for aux output
__device__ unsigned char g_ok[MROWS];
__device__ int g_coord_fmt;         // 0=int32, 1=int64, 2=float32
__device__ int g_valid_fmt;         // 0=int32, 1=uint8, 2=float32

__device__ __forceinline__ uint32_t f2tf(float f) {
    uint32_t u;
    asm("cvt.rna.tf32.f32 %0, %1;" : "=r"(u) : "f"(f));
    return u;
}

__device__ __forceinline__ void cp_async16(uint32_t s, const void* g) {
    asm volatile("cp.async.cg.shared.global [%0], [%1], 16;\n" :: "r"(s), "l"(g));
}

__device__ __forceinline__ void mma_tf32(float* c, const uint32_t* a, const uint32_t* b) {
    asm volatile(
        "mma.sync.aligned.m16n8k8.row.col.f32.tf32.tf32.f32 "
        "{%0,%1,%2,%3}, {%4,%5,%6,%7}, {%8,%9}, {%0,%1,%2,%3};\n"
        : "+f"(c[0]), "+f"(c[1]), "+f"(c[2]), "+f"(c[3])
        : "r"(a[0]), "r"(a[1]), "r"(a[2]), "r"(a[3]), "r"(b[0]), "r"(b[1]));
}

// ---------------------------------------------------------------------------
// Detect on-device dtypes of patch_coord / patch_valid from the data itself.
// coord values are in [0,64):  int64 -> all odd 32-bit words are 0 (high words)
//                              float32 -> bit patterns >= 0x10000 appear
//                              int32 -> small words, odd ones nonzero w.h.p.
// valid values are 0/1:        int32 -> bytes at off%4!=0 all zero
//                              float32 -> bytes > 1 appear (0x80/0x3f of 1.0f)
//                              uint8 -> bytes are only 0/1, nonzero ones appear
// Reads stay within the smallest possible buffer size. Single block.
// ---------------------------------------------------------------------------
__global__ void detect_kernel(const void* coordp, const void* validp) {
    __shared__ unsigned int s_or_all, s_or_odd, s_vb_or, s_vb_gt1;
    int tid = threadIdx.x;
    if (tid == 0) { s_or_all = 0; s_or_odd = 0; s_vb_or = 0; s_vb_gt1 = 0; }
    __syncthreads();

    const unsigned int* cw = (const unsigned int*)coordp;
    unsigned int oa = 0, oo = 0;
    for (int i = tid; i < 2048; i += 256) {       // first 8192 bytes (buffer >= 256KB)
        unsigned int w = cw[i];
        oa |= w;
        if (i & 1) oo |= w;
    }
    atomicOr(&s_or_all, oa);
    atomicOr(&s_or_odd, oo);

    const unsigned char* vb = (const unsigned char*)validp;
    unsigned int vo = 0, vg = 0;
    for (int i = tid; i < 4096; i += 256) {       // first 4KB (buffer >= 32KB)
        unsigned char b = vb[i];
        if (i & 3) vo |= b;
        if (b > 1) vg = 1;
    }
    atomicOr(&s_vb_or, vo);
    atomicOr(&s_vb_gt1, vg);
    __syncthreads();

    if (tid == 0) {
        int cf;
        if (s_or_all >= 0x10000u) cf = 2;          // float32
        else if (s_or_odd == 0)   cf = 1;          // int64
        else                      cf = 0;          // int32
        g_coord_fmt = cf;

        int vf;
        if (s_vb_gt1)             vf = 2;          // float32
        else if (s_vb_or == 0)    vf = 0;          // int32 (bool widened)
        else                      vf = 1;          // uint8 / native bool
        g_valid_fmt = vf;
    }
}

// ---------------------------------------------------------------------------
// Normalize coords/validity into scratch according to detected formats.
// ---------------------------------------------------------------------------
__global__ void norm_kernel(const void* coordp, const void* validp) {
    int i = blockIdx.x * blockDim.x + threadIdx.x;
    if (i >= MROWS) return;

    int cf = g_coord_fmt;
    int c0, c1;
    if (cf == 1) {
        const long long* c = (const long long*)coordp;
        c0 = (int)c[2LL * i]; c1 = (int)c[2LL * i + 1];
    } else if (cf == 2) {
        const float* c = (const float*)coordp;
        c0 = (int)c[2LL * i]; c1 = (int)c[2LL * i + 1];
    } else {
        const int* c = (const int*)coordp;
        c0 = c[2 * i]; c1 = c[2 * i + 1];
    }
    g_rawc0[i] = c0;
    g_rawc1[i] = c1;
    g_pid0[i] = c1 > 0 ? c1 : 0;   // position_ids[...,0] = coord1, clamped
    g_pid1[i] = c0 > 0 ? c0 : 0;   // position_ids[...,1] = coord0, clamped

    int vf = g_valid_fmt;
    bool v;
    if (vf == 0)      v = ((const int*)validp)[i] != 0;
    else if (vf == 2) v = ((const float*)validp)[i] != 0.0f;
    else              v = ((const unsigned char*)validp)[i] != 0;
    g_ok[i] = v ? 1 : 0;
}

// ---------------------------------------------------------------------------
// Prep: build W'[d][j] = tf32(2 * W[d][k(j)]) and bias[d] = -sum_k W[d][k]
// j = ph*48 + pw*3 + c  ->  k = c*256 + ph*16 + pw
// ---------------------------------------------------------------------------
__global__ void prep_kernel(const float* __restrict__ W) {
    int d = blockIdx.x;
    const float* wrow = W + (size_t)d * DIM;
    __shared__ float red[256];
    float s = 0.f;
    for (int j = threadIdx.x; j < DIM; j += 256) {
        int c = j % 3;
        int t = j / 3;
        int pw = t & 15;
        int ph = t >> 4;
        int k = c * 256 + ph * 16 + pw;
        float w = wrow[k];
        s += w;
        g_Wp[(size_t)d * DIM + j] = __uint_as_float(f2tf(2.0f * w));
    }
    red[threadIdx.x] = s;
    __syncthreads();
    for (int off = 128; off > 0; off >>= 1) {
        if (threadIdx.x < off) red[threadIdx.x] += red[threadIdx.x + off];
        __syncthreads();
    }
    if (threadIdx.x == 0) g_bias[d] = -red[0];
}

// ---------------------------------------------------------------------------
// Main fused GEMM: y = x @ W'^T + bias + pos(gather), tf32 warp MMA
// grid (DIM/BN=6, MROWS/BM=256), 256 threads, dynamic smem double-buffered
// ---------------------------------------------------------------------------
__global__ void __launch_bounds__(256)
gemm_kernel(const float* __restrict__ x,
            const float* __restrict__ pos_table,
            float* __restrict__ out) {
    extern __shared__ float smem[];

    const int lane = threadIdx.x & 31;
    const int warp = threadIdx.x >> 5;
    const int wm = warp & 1;   // 0..1  (m dimension, 64 rows each)
    const int wn = warp >> 1;  // 0..3  (n dimension, 32 cols each)

    float acc[4][4][4];
    #pragma unroll
    for (int a = 0; a < 4; a++)
        #pragma unroll
        for (int b = 0; b < 4; b++)
            #pragma unroll
            for (int c = 0; c < 4; c++) acc[a][b][c] = 0.f;

    const float* Abase = x + (size_t)(blockIdx.y * BM) * DIM;
    const float* Bbase = g_Wp + (size_t)(blockIdx.x * BN) * DIM;

    const int NKT = DIM / BK;  // 24

    // async load of tile kt into stage
    auto issue = [&](int kt, int stage) {
        float* As = smem + stage * STAGE_F;
        float* Bs = As + ASZ;
        const float* Ag = Abase + kt * BK;
        const float* Bg = Bbase + kt * BK;
        #pragma unroll
        for (int i = 0; i < 4; i++) {
            int linear = threadIdx.x + i * 256;
            int row = linear >> 3;
            int col4 = (linear & 7) * 4;
            uint32_t sa = (uint32_t)__cvta_generic_to_shared(&As[row * STRIDE + col4]);
            cp_async16(sa, Ag + (size_t)row * DIM + col4);
            uint32_t sb = (uint32_t)__cvta_generic_to_shared(&Bs[row * STRIDE + col4]);
            cp_async16(sb, Bg + (size_t)row * DIM + col4);
        }
        asm volatile("cp.async.commit_group;\n");
    };

    issue(0, 0);

    for (int kt = 0; kt < NKT; kt++) {
        int stage = kt & 1;
        if (kt + 1 < NKT) {
            issue(kt + 1, stage ^ 1);
            asm volatile("cp.async.wait_group 1;\n");
        } else {
            asm volatile("cp.async.wait_group 0;\n");
        }
        __syncthreads();

        const float* As = smem + stage * STAGE_F;
        const float* Bs = As + ASZ;

        #pragma unroll
        for (int ks = 0; ks < 4; ks++) {
            uint32_t af[4][4], bf[4][2];
            const int cka = ks * 8 + (lane & 3);
            #pragma unroll
            for (int im = 0; im < 4; im++) {
                int r0 = wm * 64 + im * 16 + (lane >> 2);
                af[im][0] = f2tf(As[r0 * STRIDE + cka]);
                af[im][1] = f2tf(As[(r0 + 8) * STRIDE + cka]);
                af[im][2] = f2tf(As[r0 * STRIDE + cka + 4]);
                af[im][3] = f2tf(As[(r0 + 8) * STRIDE + cka + 4]);
            }
            #pragma unroll
            for (int in = 0; in < 4; in++) {
                int n0 = wn * 32 + in * 8 + (lane >> 2);
                bf[in][0] = __float_as_uint(Bs[n0 * STRIDE + cka]);       // pre-rounded
                bf[in][1] = __float_as_uint(Bs[n0 * STRIDE + cka + 4]);
            }
            #pragma unroll
            for (int im = 0; im < 4; im++)
                #pragma unroll
                for (int in = 0; in < 4; in++)
                    mma_tf32(acc[im][in], af[im], bf[in]);
        }
        __syncthreads();
    }

    // Epilogue: + bias + pos gather (normalized indices), write float2
    const int gm0 = blockIdx.y * BM + wm * 64;
    const int gn0 = blockIdx.x * BN + wn * 32;

    #pragma unroll
    for (int im = 0; im < 4; im++) {
        int rbase = gm0 + im * 16 + (lane >> 2);
        #pragma unroll
        for (int half = 0; half < 2; half++) {
            int r = rbase + half * 8;
            int p0 = g_pid0[r];
            int p1 = g_pid1[r];
            bool v = (g_ok[r] != 0);
            const float* t0 = pos_table + (size_t)p0 * DIM;
            const float* t1 = pos_table + POS_OFF + (size_t)p1 * DIM;
            float* orow = out + (size_t)r * DIM;
            #pragma unroll
            for (int in = 0; in < 4; in++) {
                int d = gn0 + in * 8 + (lane & 3) * 2;
                float v0 = acc[im][in][half * 2 + 0] + g_bias[d];
                float v1 = acc[im][in][half * 2 + 1] + g_bias[d + 1];
                if (v) {
                    v0 += t0[d] + t1[d];
                    v1 += t0[d + 1] + t1[d + 1];
                }
                float2 o; o.x = v0; o.y = v1;
                *reinterpret_cast<float2*>(&orow[d]) = o;
            }
        }
    }
}

// ---------------------------------------------------------------------------
// Aux outputs: position_ids (reversed raw coords) + padding mask, as float32
// ---------------------------------------------------------------------------
__global__ void aux_kernel(float* __restrict__ out_pid,
                           float* __restrict__ out_pad) {
    int i = blockIdx.x * blockDim.x + threadIdx.x;
    if (i < MROWS) {
        out_pid[2LL * i]     = (float)g_rawc1[i];
        out_pid[2LL * i + 1] = (float)g_rawc0[i];
        out_pad[i] = g_ok[i] ? 0.0f : 1.0f;
    }
}

extern "C" void kernel_launch(void* const* d_in, const int* in_sizes, int n_in,
                              void* d_out, int out_size) {
    const float* x     = (const float*)d_in[0];
    const void*  coord = d_in[1];
    const void*  valid = d_in[2];
    const float* W     = (const float*)d_in[3];
    const float* pos   = (const float*)d_in[4];
    float* out = (float*)d_out;

    cudaFuncSetAttribute(gemm_kernel,
                         cudaFuncAttributeMaxDynamicSharedMemorySize, SMEM_BYTES);

    detect_kernel<<<1, 256>>>(coord, valid);
    norm_kernel<<<(MROWS + 255) / 256, 256>>>(coord, valid);
    prep_kernel<<<DIM, 256>>>(W);

    dim3 grid(DIM / BN, MROWS / BM);   // (6, 256)
    gemm_kernel<<<grid, 256, SMEM_BYTES>>>(x, pos, out);

    if ((size_t)out_size >= OUT_TOTAL) {
        aux_kernel<<<(MROWS + 255) / 256, 256>>>(
            out + OUT_Y, out + OUT_Y + OUT_PID);
    }
}